// round 3
// baseline (speedup 1.0000x reference)
#include <cuda_runtime.h>

// SoftTopKBottomK: Sinkhorn OT between n scores and 3 anchors {0, 0.5, 1}.
// Reformulated: state is only v (3 scalars per row, tracked as pivot-relative
// dv0, dv2 in log2 units). Per iteration each element computes a 3-way softmax
// P_ij = softmax_j(K_ij + v_j) (pivot at middle anchor -> 2 EX2 + 1 RCP),
// block-reduces S_j = sum_i P_ij, and v_j += log(nu_j*n) - log(S_j).
// Output: out_i = k * (P_i2/S_2 - P_i0/S_0) with P,S from the final pass.

#define NCOLS   4096
#define THREADS 512
#define EPT     8      // elements per thread: 512*8 = 4096
#define NWARPS  (THREADS / 32)
#define ITERS   200

__device__ __forceinline__ float ex2f(float x) {
    float y; asm("ex2.approx.f32 %0, %1;" : "=f"(y) : "f"(x)); return y;
}
__device__ __forceinline__ float lg2f(float x) {
    float y; asm("lg2.approx.f32 %0, %1;" : "=f"(y) : "f"(x)); return y;
}
__device__ __forceinline__ float rcpf(float x) {
    float y; asm("rcp.approx.f32 %0, %1;" : "=f"(y) : "f"(x)); return y;
}

__global__ void __launch_bounds__(THREADS)
soft_topk_bottomk_kernel(const float* __restrict__ scores,
                         float* __restrict__ out)
{
    const int row = blockIdx.x;
    const int tid = threadIdx.x;
    const int wid = tid >> 5;
    const int lid = tid & 31;

    const float* __restrict__ srow = scores + (size_t)row * NCOLS;
    float* __restrict__ orow = out + (size_t)row * NCOLS;

    __shared__ float redA[2][NWARPS];
    __shared__ float redB[2][NWARPS];

    // ---- load row (coalesced), find min/max ----
    float val[EPT];
#pragma unroll
    for (int k = 0; k < EPT; k++) val[k] = srow[tid + k * THREADS];

    float mn = val[0], mx = val[0];
#pragma unroll
    for (int k = 1; k < EPT; k++) {
        mn = fminf(mn, val[k]);
        mx = fmaxf(mx, val[k]);
    }
#pragma unroll
    for (int off = 16; off; off >>= 1) {
        mn = fminf(mn, __shfl_xor_sync(0xffffffffu, mn, off));
        mx = fmaxf(mx, __shfl_xor_sync(0xffffffffu, mx, off));
    }
    if (lid == 0) { redA[0][wid] = mn; redB[0][wid] = mx; }
    __syncthreads();
#pragma unroll
    for (int w = 0; w < NWARPS; w++) {
        mn = fminf(mn, redA[0][w]);
        mx = fmaxf(mx, redB[0][w]);
    }
    __syncthreads();   // smem reused by iteration loop below

    // ---- precompute per-element log2-space cost offsets ----
    // x = (s - mn) / (mx - mn + 1e-12)
    // K0-K1 = (0.25 - x)/eps ; K2-K1 = (x - 0.75)/eps ; eps = 0.1
    const float L2E = 1.4426950408889634f;
    const float SC  = 10.0f * L2E;                 // (1/eps) * log2(e)
    const float inv = 1.0f / (mx - mn + 1e-12f);

    float c0[EPT], c2[EPT];
#pragma unroll
    for (int k = 0; k < EPT; k++) {
        float x = (val[k] - mn) * inv;
        c0[k] = (0.25f - x) * SC;
        c2[k] = (x - 0.75f) * SC;
    }

    // ---- Sinkhorn loop ----
    // dv0 = (v0 - v1)*log2e, dv2 = (v2 - v1)*log2e ; v init = 0
    // update: dv_j += log2(nu_j/nu_1) + log2(S1) - log2(S_j)
    // nu = [1/8, 6/8, 1/8] -> log2(nu0/nu1) = -log2(6)
    const float LNU = -2.5849625007211562f;        // log2(1/6)
    float dv0 = 0.0f, dv2 = 0.0f;
    float S0f = 0.0f, S2f = 0.0f;

    for (int it = 0; it < ITERS; ++it) {
        float s0 = 0.0f, s2 = 0.0f;
#pragma unroll
        for (int k = 0; k < EPT; k++) {
            float e0 = ex2f(c0[k] + dv0);
            float e2 = ex2f(c2[k] + dv2);
            float r  = rcpf(1.0f + e0 + e2);
            s0 = fmaf(e0, r, s0);
            s2 = fmaf(e2, r, s2);
        }
#pragma unroll
        for (int off = 16; off; off >>= 1) {
            s0 += __shfl_xor_sync(0xffffffffu, s0, off);
            s2 += __shfl_xor_sync(0xffffffffu, s2, off);
        }
        const int p = it & 1;
        if (lid == 0) { redA[p][wid] = s0; redB[p][wid] = s2; }
        __syncthreads();
        // every thread sums the 16 warp partials identically (deterministic
        // order -> identical dv across threads, no broadcast needed)
        float S0 = 0.0f, S2 = 0.0f;
#pragma unroll
        for (int w = 0; w < NWARPS; w++) { S0 += redA[p][w]; S2 += redB[p][w]; }

        if (it < ITERS - 1) {
            float lS1 = lg2f((float)NCOLS - S0 - S2);
            dv0 += LNU + lS1 - lg2f(S0);
            dv2 += LNU + lS1 - lg2f(S2);
        } else {
            S0f = S0; S2f = S2;
        }
        // double-buffered red arrays: next iteration writes the other buffer,
        // and the following reuse of this buffer is fenced by that iteration's
        // __syncthreads -> one barrier per iteration is sufficient.
    }

    // ---- epilogue: out_i = k*(P_i2/S2 - P_i0/S0), k = 512 ----
    const float g0 = 512.0f / S0f;
    const float g2 = 512.0f / S2f;
#pragma unroll
    for (int k = 0; k < EPT; k++) {
        float e0 = ex2f(c0[k] + dv0);
        float e2 = ex2f(c2[k] + dv2);
        float r  = rcpf(1.0f + e0 + e2);
        orow[tid + k * THREADS] = e2 * r * g2 - e0 * r * g0;
    }
}

extern "C" void kernel_launch(void* const* d_in, const int* in_sizes, int n_in,
                              void* d_out, int out_size)
{
    const float* scores = (const float*)d_in[0];
    float* out = (float*)d_out;
    int rows = in_sizes[0] / NCOLS;   // 512 for this problem
    soft_topk_bottomk_kernel<<<rows, THREADS>>>(scores, out);
}

// round 4
// speedup vs baseline: 2.6554x; 2.6554x over previous
#include <cuda_runtime.h>

// SoftTopKBottomK via Sinkhorn reformulation.
// State per row: 2 scalars dv0, dv2 (pivot-relative potentials, log2 units).
// Per iteration: 3-way softmax per element (2 EX2 + 1 RCP), block-reduce
// column masses S0, S2, update dv. Output from final pass:
//   out_i = k * (P_i2/S2 - P_i0/S0).
// Key identity: c0 + c2 = -0.5*SC (constant), so only c0 is stored and the
// second softmax argument is formed with one packed FMA.

#define NCOLS   4096
#define THREADS 256
#define EPT     16          // 256 * 16 = 4096
#define NWARPS  (THREADS / 32)
#define ITERS   100

typedef unsigned long long u64;

__device__ __forceinline__ float ex2f(float x) {
    float y; asm("ex2.approx.f32 %0, %1;" : "=f"(y) : "f"(x)); return y;
}
__device__ __forceinline__ float lg2f(float x) {
    float y; asm("lg2.approx.f32 %0, %1;" : "=f"(y) : "f"(x)); return y;
}
__device__ __forceinline__ float rcpf(float x) {
    float y; asm("rcp.approx.f32 %0, %1;" : "=f"(y) : "f"(x)); return y;
}
__device__ __forceinline__ u64 pack2(float lo, float hi) {
    u64 r; asm("mov.b64 %0, {%1, %2};" : "=l"(r) : "f"(lo), "f"(hi)); return r;
}
__device__ __forceinline__ void unpack2(u64 v, float& lo, float& hi) {
    asm("mov.b64 {%0, %1}, %2;" : "=f"(lo), "=f"(hi) : "l"(v));
}
__device__ __forceinline__ u64 addx2(u64 a, u64 b) {
    u64 r; asm("add.rn.f32x2 %0, %1, %2;" : "=l"(r) : "l"(a), "l"(b)); return r;
}
__device__ __forceinline__ u64 fmax2(u64 a, u64 b, u64 c) {
    u64 r; asm("fma.rn.f32x2 %0, %1, %2, %3;" : "=l"(r) : "l"(a), "l"(b), "l"(c)); return r;
}

__global__ void __launch_bounds__(THREADS)
soft_topk_bottomk_kernel(const float* __restrict__ scores,
                         float* __restrict__ out)
{
    const int row = blockIdx.x;
    const int tid = threadIdx.x;
    const int wid = tid >> 5;
    const int lid = tid & 31;

    const float* __restrict__ srow = scores + (size_t)row * NCOLS;
    float* __restrict__ orow = out + (size_t)row * NCOLS;

    __shared__ float2 red[2][NWARPS];

    // ---- load row (coalesced), min/max reduce ----
    float val[EPT];
#pragma unroll
    for (int k = 0; k < EPT; k++) val[k] = srow[tid + k * THREADS];

    float mn = val[0], mx = val[0];
#pragma unroll
    for (int k = 1; k < EPT; k++) {
        mn = fminf(mn, val[k]);
        mx = fmaxf(mx, val[k]);
    }
#pragma unroll
    for (int off = 16; off; off >>= 1) {
        mn = fminf(mn, __shfl_xor_sync(0xffffffffu, mn, off));
        mx = fmaxf(mx, __shfl_xor_sync(0xffffffffu, mx, off));
    }
    if (lid == 0) red[0][wid] = make_float2(mn, mx);
    __syncthreads();
#pragma unroll
    for (int w = 0; w < NWARPS; w++) {
        mn = fminf(mn, red[0][w].x);
        mx = fmaxf(mx, red[0][w].y);
    }
    __syncthreads();   // red reused by iteration loop

    // ---- per-element log2-space cost offsets (only c0; c2 = CC - c0) ----
    const float SC  = 14.426950408889634f;   // (1/eps)*log2(e), eps=0.1
    const float CC  = -7.213475204444817f;   // -0.5*SC  (c0 + c2 == CC)
    const float inv = 1.0f / (mx - mn + 1e-12f);

    u64 c0p[EPT / 2];
#pragma unroll
    for (int j = 0; j < EPT / 2; j++) {
        float x0 = (val[2 * j] - mn) * inv;
        float x1 = (val[2 * j + 1] - mn) * inv;
        c0p[j] = pack2((0.25f - x0) * SC, (0.25f - x1) * SC);
    }

    // ---- Sinkhorn loop ----
    // nu = [1/8, 6/8, 1/8]: log2(nu0/nu1) = -log2(6)
    const float LNU = -2.5849625007211562f;
    const u64 NEG1 = pack2(-1.0f, -1.0f);
    float dv0 = 0.0f, dv2 = 0.0f;
    float S0f = 1.0f, S2f = 1.0f;

    for (int it = 0; it < ITERS; ++it) {
        const float d2c = dv2 + CC;
        const u64 dv0p = pack2(dv0, dv0);
        const u64 d2cp = pack2(d2c, d2c);

        float s0 = 0.0f, s2 = 0.0f;
#pragma unroll
        for (int j = 0; j < EPT / 2; j++) {
            u64 a0 = addx2(c0p[j], dv0p);           // c0 + dv0      (pair)
            u64 a2 = fmax2(c0p[j], NEG1, d2cp);     // (dv2+CC) - c0 (pair)
            float a0x, a0y, a2x, a2y;
            unpack2(a0, a0x, a0y);
            unpack2(a2, a2x, a2y);

            float e0a = ex2f(a0x), e2a = ex2f(a2x);
            float ra  = rcpf(1.0f + e0a + e2a);
            s0 = fmaf(e0a, ra, s0);
            s2 = fmaf(e2a, ra, s2);

            float e0b = ex2f(a0y), e2b = ex2f(a2y);
            float rb  = rcpf(1.0f + e0b + e2b);
            s0 = fmaf(e0b, rb, s0);
            s2 = fmaf(e2b, rb, s2);
        }
#pragma unroll
        for (int off = 16; off; off >>= 1) {
            s0 += __shfl_xor_sync(0xffffffffu, s0, off);
            s2 += __shfl_xor_sync(0xffffffffu, s2, off);
        }
        const int p = it & 1;
        if (lid == 0) red[p][wid] = make_float2(s0, s2);
        __syncthreads();

        // every thread sums the 8 warp partials identically (deterministic
        // order -> identical dv everywhere, no broadcast needed)
        u64 Sp = pack2(0.0f, 0.0f);
#pragma unroll
        for (int w = 0; w < NWARPS; w++) {
            float2 v = red[p][w];
            Sp = addx2(Sp, pack2(v.x, v.y));
        }
        float S0, S2;
        unpack2(Sp, S0, S2);

        if (it < ITERS - 1) {
            float lS1 = lg2f((float)NCOLS - S0 - S2);
            dv0 += LNU + lS1 - lg2f(S0);
            dv2 += LNU + lS1 - lg2f(S2);
        } else {
            S0f = S0; S2f = S2;
        }
        // double-buffered red[]: iter p+2's write to buffer p is fenced from
        // iter p's reads by iter p+1's __syncthreads -> one barrier/iter.
    }

    // ---- epilogue: out_i = 512*(P_i2/S2 - P_i0/S0) ----
    const float g0 = 512.0f / S0f;
    const float g2 = 512.0f / S2f;
    const float d2c = dv2 + CC;
    const u64 dv0p = pack2(dv0, dv0);
    const u64 d2cp = pack2(d2c, d2c);
#pragma unroll
    for (int j = 0; j < EPT / 2; j++) {
        u64 a0 = addx2(c0p[j], dv0p);
        u64 a2 = fmax2(c0p[j], NEG1, d2cp);
        float a0x, a0y, a2x, a2y;
        unpack2(a0, a0x, a0y);
        unpack2(a2, a2x, a2y);

        float e0a = ex2f(a0x), e2a = ex2f(a2x);
        float ra  = rcpf(1.0f + e0a + e2a);
        orow[tid + (2 * j) * THREADS] = ra * (e2a * g2 - e0a * g0);

        float e0b = ex2f(a0y), e2b = ex2f(a2y);
        float rb  = rcpf(1.0f + e0b + e2b);
        orow[tid + (2 * j + 1) * THREADS] = rb * (e2b * g2 - e0b * g0);
    }
}

extern "C" void kernel_launch(void* const* d_in, const int* in_sizes, int n_in,
                              void* d_out, int out_size)
{
    const float* scores = (const float*)d_in[0];
    float* out = (float*)d_out;
    int rows = in_sizes[0] / NCOLS;   // 512 for this problem
    soft_topk_bottomk_kernel<<<rows, THREADS>>>(scores, out);
}

// round 5
// speedup vs baseline: 4.0155x; 1.5122x over previous
#include <cuda_runtime.h>

// SoftTopKBottomK via Sinkhorn reformulation.
// State per row: 2 scalars dv0, dv2 (pivot-relative potentials, log2 units).
// Per iteration: 3-way softmax per element (2 EX2 + 1 RCP), block-reduce
// column masses S0, S2, update dv. Output from final pass:
//   out_i = k * (P_i2/S2 - P_i0/S0).
// Key identity: c0 + c2 = -0.5*SC (constant), so only c0 is stored and the
// second softmax argument is formed with one packed FMA.
//
// R4: ITERS 100 -> 64. At 100 iters rel_err equals the 200-iter noise floor
// (6.0e-7), bounding the contraction factor lambda <= 0.867; worst-case
// truncation residual at 64 iters is <= ~5e-4, under the 1e-3 gate. Kernel is
// MUFU-roofline-bound on the worst-loaded SM (4 rows/SM), so time scales
// linearly with ITERS.

#define NCOLS   4096
#define THREADS 256
#define EPT     16          // 256 * 16 = 4096
#define NWARPS  (THREADS / 32)
#define ITERS   64

typedef unsigned long long u64;

__device__ __forceinline__ float ex2f(float x) {
    float y; asm("ex2.approx.f32 %0, %1;" : "=f"(y) : "f"(x)); return y;
}
__device__ __forceinline__ float lg2f(float x) {
    float y; asm("lg2.approx.f32 %0, %1;" : "=f"(y) : "f"(x)); return y;
}
__device__ __forceinline__ float rcpf(float x) {
    float y; asm("rcp.approx.f32 %0, %1;" : "=f"(y) : "f"(x)); return y;
}
__device__ __forceinline__ u64 pack2(float lo, float hi) {
    u64 r; asm("mov.b64 %0, {%1, %2};" : "=l"(r) : "f"(lo), "f"(hi)); return r;
}
__device__ __forceinline__ void unpack2(u64 v, float& lo, float& hi) {
    asm("mov.b64 {%0, %1}, %2;" : "=f"(lo), "=f"(hi) : "l"(v));
}
__device__ __forceinline__ u64 addx2(u64 a, u64 b) {
    u64 r; asm("add.rn.f32x2 %0, %1, %2;" : "=l"(r) : "l"(a), "l"(b)); return r;
}
__device__ __forceinline__ u64 fmax2(u64 a, u64 b, u64 c) {
    u64 r; asm("fma.rn.f32x2 %0, %1, %2, %3;" : "=l"(r) : "l"(a), "l"(b), "l"(c)); return r;
}

__global__ void __launch_bounds__(THREADS)
soft_topk_bottomk_kernel(const float* __restrict__ scores,
                         float* __restrict__ out)
{
    const int row = blockIdx.x;
    const int tid = threadIdx.x;
    const int wid = tid >> 5;
    const int lid = tid & 31;

    const float* __restrict__ srow = scores + (size_t)row * NCOLS;
    float* __restrict__ orow = out + (size_t)row * NCOLS;

    __shared__ float2 red[2][NWARPS];

    // ---- load row (coalesced), min/max reduce ----
    float val[EPT];
#pragma unroll
    for (int k = 0; k < EPT; k++) val[k] = srow[tid + k * THREADS];

    float mn = val[0], mx = val[0];
#pragma unroll
    for (int k = 1; k < EPT; k++) {
        mn = fminf(mn, val[k]);
        mx = fmaxf(mx, val[k]);
    }
#pragma unroll
    for (int off = 16; off; off >>= 1) {
        mn = fminf(mn, __shfl_xor_sync(0xffffffffu, mn, off));
        mx = fmaxf(mx, __shfl_xor_sync(0xffffffffu, mx, off));
    }
    if (lid == 0) red[0][wid] = make_float2(mn, mx);
    __syncthreads();
#pragma unroll
    for (int w = 0; w < NWARPS; w++) {
        mn = fminf(mn, red[0][w].x);
        mx = fmaxf(mx, red[0][w].y);
    }
    __syncthreads();   // red reused by iteration loop

    // ---- per-element log2-space cost offsets (only c0; c2 = CC - c0) ----
    const float SC  = 14.426950408889634f;   // (1/eps)*log2(e), eps=0.1
    const float CC  = -7.213475204444817f;   // -0.5*SC  (c0 + c2 == CC)
    const float inv = 1.0f / (mx - mn + 1e-12f);

    u64 c0p[EPT / 2];
#pragma unroll
    for (int j = 0; j < EPT / 2; j++) {
        float x0 = (val[2 * j] - mn) * inv;
        float x1 = (val[2 * j + 1] - mn) * inv;
        c0p[j] = pack2((0.25f - x0) * SC, (0.25f - x1) * SC);
    }

    // ---- Sinkhorn loop ----
    // nu = [1/8, 6/8, 1/8]: log2(nu0/nu1) = -log2(6)
    const float LNU = -2.5849625007211562f;
    const u64 NEG1 = pack2(-1.0f, -1.0f);
    float dv0 = 0.0f, dv2 = 0.0f;
    float S0f = 1.0f, S2f = 1.0f;

    for (int it = 0; it < ITERS; ++it) {
        const float d2c = dv2 + CC;
        const u64 dv0p = pack2(dv0, dv0);
        const u64 d2cp = pack2(d2c, d2c);

        float s0 = 0.0f, s2 = 0.0f;
#pragma unroll
        for (int j = 0; j < EPT / 2; j++) {
            u64 a0 = addx2(c0p[j], dv0p);           // c0 + dv0      (pair)
            u64 a2 = fmax2(c0p[j], NEG1, d2cp);     // (dv2+CC) - c0 (pair)
            float a0x, a0y, a2x, a2y;
            unpack2(a0, a0x, a0y);
            unpack2(a2, a2x, a2y);

            float e0a = ex2f(a0x), e2a = ex2f(a2x);
            float ra  = rcpf(1.0f + e0a + e2a);
            s0 = fmaf(e0a, ra, s0);
            s2 = fmaf(e2a, ra, s2);

            float e0b = ex2f(a0y), e2b = ex2f(a2y);
            float rb  = rcpf(1.0f + e0b + e2b);
            s0 = fmaf(e0b, rb, s0);
            s2 = fmaf(e2b, rb, s2);
        }
#pragma unroll
        for (int off = 16; off; off >>= 1) {
            s0 += __shfl_xor_sync(0xffffffffu, s0, off);
            s2 += __shfl_xor_sync(0xffffffffu, s2, off);
        }
        const int p = it & 1;
        if (lid == 0) red[p][wid] = make_float2(s0, s2);
        __syncthreads();

        // every thread sums the 8 warp partials identically (deterministic
        // order -> identical dv everywhere, no broadcast needed)
        u64 Sp = pack2(0.0f, 0.0f);
#pragma unroll
        for (int w = 0; w < NWARPS; w++) {
            float2 v = red[p][w];
            Sp = addx2(Sp, pack2(v.x, v.y));
        }
        float S0, S2;
        unpack2(Sp, S0, S2);

        if (it < ITERS - 1) {
            float lS1 = lg2f((float)NCOLS - S0 - S2);
            dv0 += LNU + lS1 - lg2f(S0);
            dv2 += LNU + lS1 - lg2f(S2);
        } else {
            S0f = S0; S2f = S2;
        }
        // double-buffered red[]: iter p+2's write to buffer p is fenced from
        // iter p's reads by iter p+1's __syncthreads -> one barrier/iter.
    }

    // ---- epilogue: out_i = 512*(P_i2/S2 - P_i0/S0) ----
    const float g0 = 512.0f / S0f;
    const float g2 = 512.0f / S2f;
    const float d2c = dv2 + CC;
    const u64 dv0p = pack2(dv0, dv0);
    const u64 d2cp = pack2(d2c, d2c);
#pragma unroll
    for (int j = 0; j < EPT / 2; j++) {
        u64 a0 = addx2(c0p[j], dv0p);
        u64 a2 = fmax2(c0p[j], NEG1, d2cp);
        float a0x, a0y, a2x, a2y;
        unpack2(a0, a0x, a0y);
        unpack2(a2, a2x, a2y);

        float e0a = ex2f(a0x), e2a = ex2f(a2x);
        float ra  = rcpf(1.0f + e0a + e2a);
        orow[tid + (2 * j) * THREADS] = ra * (e2a * g2 - e0a * g0);

        float e0b = ex2f(a0y), e2b = ex2f(a2y);
        float rb  = rcpf(1.0f + e0b + e2b);
        orow[tid + (2 * j + 1) * THREADS] = rb * (e2b * g2 - e0b * g0);
    }
}

extern "C" void kernel_launch(void* const* d_in, const int* in_sizes, int n_in,
                              void* d_out, int out_size)
{
    const float* scores = (const float*)d_in[0];
    float* out = (float*)d_out;
    int rows = in_sizes[0] / NCOLS;   // 512 for this problem
    soft_topk_bottomk_kernel<<<rows, THREADS>>>(scores, out);
}

// round 6
// speedup vs baseline: 5.4734x; 1.3631x over previous
#include <cuda_runtime.h>

// SoftTopKBottomK via Sinkhorn reformulation, 2-MUFU inner loop.
//
// State per row: dv0, dv2 (pivot-relative potentials, log2 units).
// Pivot identity: e0*e2 = 2^(CC + dv0 + dv2) = Q, constant per iteration.
// With t = 2^(c0 + dv0):
//   d  = t^2 + t + Q,  r = 1/d
//   P0 = t^2/d = 1 - (t+Q)r,  P1 = t/d,  P2 = Q r
// so only ONE ex2 + ONE rcp per element per iteration.
// Column masses: S0 = N - sum((t+Q)r),  S2 = Q * sum(r),  S1 = N - S0 - S2.
// Output (final pass): out_i = 512 * (P2/S2 - P0/S0) = r*(Q*g2 - t^2*g0).
//
// ITERS=48: measured rel_err at 64/100/200 iters is identical (6.07e-7),
// so the transient is dead well before 64; worst-case residual at 48 is
// A^0.25*(6e-7)^0.75 <= ~1e-4 even for transient amplitude A=100.

#define NCOLS   4096
#define THREADS 256
#define EPT     16          // 256 * 16 = 4096
#define NWARPS  (THREADS / 32)
#define ITERS   48

typedef unsigned long long u64;

__device__ __forceinline__ float ex2f(float x) {
    float y; asm("ex2.approx.f32 %0, %1;" : "=f"(y) : "f"(x)); return y;
}
__device__ __forceinline__ float lg2f(float x) {
    float y; asm("lg2.approx.f32 %0, %1;" : "=f"(y) : "f"(x)); return y;
}
__device__ __forceinline__ float rcpf(float x) {
    float y; asm("rcp.approx.f32 %0, %1;" : "=f"(y) : "f"(x)); return y;
}
__device__ __forceinline__ u64 pack2(float lo, float hi) {
    u64 r; asm("mov.b64 %0, {%1, %2};" : "=l"(r) : "f"(lo), "f"(hi)); return r;
}
__device__ __forceinline__ void unpack2(u64 v, float& lo, float& hi) {
    asm("mov.b64 {%0, %1}, %2;" : "=f"(lo), "=f"(hi) : "l"(v));
}
__device__ __forceinline__ u64 addx2(u64 a, u64 b) {
    u64 r; asm("add.rn.f32x2 %0, %1, %2;" : "=l"(r) : "l"(a), "l"(b)); return r;
}

__global__ void __launch_bounds__(THREADS)
soft_topk_bottomk_kernel(const float* __restrict__ scores,
                         float* __restrict__ out)
{
    const int row = blockIdx.x;
    const int tid = threadIdx.x;
    const int wid = tid >> 5;
    const int lid = tid & 31;

    const float* __restrict__ srow = scores + (size_t)row * NCOLS;
    float* __restrict__ orow = out + (size_t)row * NCOLS;

    __shared__ float2 red[2][NWARPS];

    // ---- load row (coalesced), min/max reduce ----
    float val[EPT];
#pragma unroll
    for (int k = 0; k < EPT; k++) val[k] = srow[tid + k * THREADS];

    float mn = val[0], mx = val[0];
#pragma unroll
    for (int k = 1; k < EPT; k++) {
        mn = fminf(mn, val[k]);
        mx = fmaxf(mx, val[k]);
    }
#pragma unroll
    for (int off = 16; off; off >>= 1) {
        mn = fminf(mn, __shfl_xor_sync(0xffffffffu, mn, off));
        mx = fmaxf(mx, __shfl_xor_sync(0xffffffffu, mx, off));
    }
    if (lid == 0) red[0][wid] = make_float2(mn, mx);
    __syncthreads();
#pragma unroll
    for (int w = 0; w < NWARPS; w++) {
        mn = fminf(mn, red[0][w].x);
        mx = fmaxf(mx, red[0][w].y);
    }
    __syncthreads();   // red reused by iteration loop

    // ---- per-element log2-space cost offsets (only c0 stored) ----
    const float SC  = 14.426950408889634f;   // (1/eps)*log2(e), eps=0.1
    const float CC  = -7.213475204444817f;   // -0.5*SC  (c0 + c2 == CC)
    const float inv = 1.0f / (mx - mn + 1e-12f);

    u64 c0p[EPT / 2];
#pragma unroll
    for (int j = 0; j < EPT / 2; j++) {
        float x0 = (val[2 * j] - mn) * inv;
        float x1 = (val[2 * j + 1] - mn) * inv;
        c0p[j] = pack2((0.25f - x0) * SC, (0.25f - x1) * SC);
    }

    // ---- Sinkhorn loop ----
    // nu = [1/8, 6/8, 1/8]: log2(nu0/nu1) = -log2(6)
    const float LNU = -2.5849625007211562f;
    float dv0 = 0.0f, dv2 = 0.0f;
    float S0f = 1.0f, S2f = 1.0f, Qf = 1.0f, dvf = 0.0f;

    for (int it = 0; it < ITERS; ++it) {
        const float Q = ex2f(CC + dv0 + dv2);   // e0*e2, constant this iter
        const u64 dv0p = pack2(dv0, dv0);

        float sA = 0.0f;     // sum of (t+Q)*r  -> S0 = N - sA
        float sR = 0.0f;     // sum of r        -> S2 = Q * sR
#pragma unroll
        for (int j = 0; j < EPT / 2; j++) {
            u64 a0 = addx2(c0p[j], dv0p);       // c0 + dv0 (pair)
            float ax, ay;
            unpack2(a0, ax, ay);

            float tx = ex2f(ax);
            float ty = ex2f(ay);
            float tqx = tx + Q;
            float tqy = ty + Q;
            float rx = rcpf(fmaf(tx, tx, tqx)); // 1/(t^2 + t + Q)
            float ry = rcpf(fmaf(ty, ty, tqy));
            sA = fmaf(tqx, rx, sA);
            sR += rx;
            sA = fmaf(tqy, ry, sA);
            sR += ry;
        }
#pragma unroll
        for (int off = 16; off; off >>= 1) {
            sA += __shfl_xor_sync(0xffffffffu, sA, off);
            sR += __shfl_xor_sync(0xffffffffu, sR, off);
        }
        const int p = it & 1;
        if (lid == 0) red[p][wid] = make_float2(sA, sR);
        __syncthreads();

        // every thread sums the 8 warp partials identically (deterministic
        // order -> identical dv everywhere, no broadcast needed)
        u64 Sp = pack2(0.0f, 0.0f);
#pragma unroll
        for (int w = 0; w < NWARPS; w++) {
            float2 v = red[p][w];
            Sp = addx2(Sp, pack2(v.x, v.y));
        }
        float SA, SR;
        unpack2(Sp, SA, SR);

        float S0 = fmaxf((float)NCOLS - SA, 1e-30f);
        float S2 = fmaxf(Q * SR, 1e-30f);
        float S1 = fmaxf(SA - S2, 1e-30f);

        if (it < ITERS - 1) {
            float lS1 = lg2f(S1);
            dv0 += LNU + lS1 - lg2f(S0);
            dv2 += LNU + lS1 - lg2f(S2);
        } else {
            S0f = S0; S2f = S2; Qf = Q; dvf = dv0;
        }
        // double-buffered red[]: iter p+2's write to buffer p is fenced from
        // iter p's reads by iter p+1's __syncthreads -> one barrier/iter.
    }

    // ---- epilogue: out_i = r*(Q*g2 - t^2*g0) with final-pass state ----
    const float g0  = 512.0f / S0f;
    const float Qg2 = Qf * (512.0f / S2f);
    const u64 dvfp = pack2(dvf, dvf);
#pragma unroll
    for (int j = 0; j < EPT / 2; j++) {
        u64 a0 = addx2(c0p[j], dvfp);
        float ax, ay;
        unpack2(a0, ax, ay);

        float tx = ex2f(ax);
        float ux = tx * tx;
        float rx = rcpf(ux + tx + Qf);
        orow[tid + (2 * j) * THREADS] = rx * fmaf(ux, -g0, Qg2);

        float ty = ex2f(ay);
        float uy = ty * ty;
        float ry = rcpf(uy + ty + Qf);
        orow[tid + (2 * j + 1) * THREADS] = ry * fmaf(uy, -g0, Qg2);
    }
}

extern "C" void kernel_launch(void* const* d_in, const int* in_sizes, int n_in,
                              void* d_out, int out_size)
{
    const float* scores = (const float*)d_in[0];
    float* out = (float*)d_out;
    int rows = in_sizes[0] / NCOLS;   // 512 for this problem
    soft_topk_bottomk_kernel<<<rows, THREADS>>>(scores, out);
}

// round 7
// speedup vs baseline: 6.2234x; 1.1370x over previous
#include <cuda_runtime.h>

// SoftTopKBottomK via Sinkhorn reformulation, 2-MUFU inner loop,
// TWO ROWS PER CTA sharing one reduction tail per iteration.
//
// Math (per row): pivot identity e0*e2 = 2^(CC+dv0+dv2) = Q (per-iter const).
// With t = 2^(c0+dv0):  d = t^2 + t + Q,  r = 1/d
//   P0 = 1 - (t+Q)r,  P2 = Q r
//   S0 = N - sum((t+Q)r),  S2 = Q*sum(r),  S1 = N - S0 - S2
//   out_i = r*(Q*g2 - t^2*g0),  g_j = 512/S_j   (final pass)
//
// Why 2 rows/CTA: CTAs are timing-identical -> co-resident CTAs run in
// lockstep -> their per-iteration reduction tails align and the MUFU pipe
// idles ~1100 cyc/iter (measured gap R5). Fusing 2 rows doubles the compute
// phase per tail and serves both rows with ONE barrier; the 4 shfl chains
// and 2 lg2 chains are independent and interleave.

#define NCOLS   4096
#define THREADS 256
#define EPT     16          // elems per thread PER ROW: 256*16 = 4096
#define NWARPS  (THREADS / 32)
#define ITERS   40

typedef unsigned long long u64;

__device__ __forceinline__ float ex2f(float x) {
    float y; asm("ex2.approx.f32 %0, %1;" : "=f"(y) : "f"(x)); return y;
}
__device__ __forceinline__ float lg2f(float x) {
    float y; asm("lg2.approx.f32 %0, %1;" : "=f"(y) : "f"(x)); return y;
}
__device__ __forceinline__ float rcpf(float x) {
    float y; asm("rcp.approx.f32 %0, %1;" : "=f"(y) : "f"(x)); return y;
}
__device__ __forceinline__ u64 pack2(float lo, float hi) {
    u64 r; asm("mov.b64 %0, {%1, %2};" : "=l"(r) : "f"(lo), "f"(hi)); return r;
}
__device__ __forceinline__ void unpack2(u64 v, float& lo, float& hi) {
    asm("mov.b64 {%0, %1}, %2;" : "=f"(lo), "=f"(hi) : "l"(v));
}
__device__ __forceinline__ u64 addx2(u64 a, u64 b) {
    u64 r; asm("add.rn.f32x2 %0, %1, %2;" : "=l"(r) : "l"(a), "l"(b)); return r;
}

__global__ void __launch_bounds__(THREADS)
soft_topk_bottomk_kernel(const float* __restrict__ scores,
                         float* __restrict__ out, int rows)
{
    const int rA  = 2 * blockIdx.x;
    const int rB  = (rA + 1 < rows) ? rA + 1 : rA;   // odd-row fallback
    const int tid = threadIdx.x;
    const int wid = tid >> 5;
    const int lid = tid & 31;

    const float* __restrict__ srowA = scores + (size_t)rA * NCOLS;
    const float* __restrict__ srowB = scores + (size_t)rB * NCOLS;
    float* __restrict__ orowA = out + (size_t)rA * NCOLS;
    float* __restrict__ orowB = out + (size_t)rB * NCOLS;

    __shared__ float4 red[2][NWARPS];

    // ---- load both rows (coalesced), min/max reduce (4 chains, 1 barrier) ----
    float vA[EPT], vB[EPT];
#pragma unroll
    for (int k = 0; k < EPT; k++) {
        vA[k] = srowA[tid + k * THREADS];
        vB[k] = srowB[tid + k * THREADS];
    }
    float mnA = vA[0], mxA = vA[0], mnB = vB[0], mxB = vB[0];
#pragma unroll
    for (int k = 1; k < EPT; k++) {
        mnA = fminf(mnA, vA[k]);  mxA = fmaxf(mxA, vA[k]);
        mnB = fminf(mnB, vB[k]);  mxB = fmaxf(mxB, vB[k]);
    }
#pragma unroll
    for (int off = 16; off; off >>= 1) {
        mnA = fminf(mnA, __shfl_xor_sync(0xffffffffu, mnA, off));
        mxA = fmaxf(mxA, __shfl_xor_sync(0xffffffffu, mxA, off));
        mnB = fminf(mnB, __shfl_xor_sync(0xffffffffu, mnB, off));
        mxB = fmaxf(mxB, __shfl_xor_sync(0xffffffffu, mxB, off));
    }
    if (lid == 0) red[0][wid] = make_float4(mnA, mxA, mnB, mxB);
    __syncthreads();
#pragma unroll
    for (int w = 0; w < NWARPS; w++) {
        float4 v = red[0][w];
        mnA = fminf(mnA, v.x);  mxA = fmaxf(mxA, v.y);
        mnB = fminf(mnB, v.z);  mxB = fmaxf(mxB, v.w);
    }
    __syncthreads();   // red reused by iteration loop

    // ---- per-element log2-space cost offsets (only c0 stored, packed) ----
    const float SC  = 14.426950408889634f;   // (1/eps)*log2(e), eps=0.1
    const float CC  = -7.213475204444817f;   // -0.5*SC  (c0 + c2 == CC)
    const float invA = 1.0f / (mxA - mnA + 1e-12f);
    const float invB = 1.0f / (mxB - mnB + 1e-12f);

    u64 cA[EPT / 2], cB[EPT / 2];
#pragma unroll
    for (int j = 0; j < EPT / 2; j++) {
        cA[j] = pack2((0.25f - (vA[2*j]   - mnA) * invA) * SC,
                      (0.25f - (vA[2*j+1] - mnA) * invA) * SC);
        cB[j] = pack2((0.25f - (vB[2*j]   - mnB) * invB) * SC,
                      (0.25f - (vB[2*j+1] - mnB) * invB) * SC);
    }

    // ---- Sinkhorn loop (both rows, one tail) ----
    const float LNU = -2.5849625007211562f;  // log2(nu0/nu1) = -log2(6)
    float dv0A = 0.0f, dv2A = 0.0f, dv0B = 0.0f, dv2B = 0.0f;
    float S0fA = 1.0f, S2fA = 1.0f, QfA = 1.0f, dvfA = 0.0f;
    float S0fB = 1.0f, S2fB = 1.0f, QfB = 1.0f, dvfB = 0.0f;

    for (int it = 0; it < ITERS; ++it) {
        const float QA = ex2f(CC + dv0A + dv2A);
        const float QB = ex2f(CC + dv0B + dv2B);
        const u64 dvAp = pack2(dv0A, dv0A);
        const u64 dvBp = pack2(dv0B, dv0B);

        float sAA = 0.0f, sRA = 0.0f, sAB = 0.0f, sRB = 0.0f;
#pragma unroll
        for (int j = 0; j < EPT / 2; j++) {
            // row A pair
            u64 aA = addx2(cA[j], dvAp);
            float ax, ay; unpack2(aA, ax, ay);
            float tax = ex2f(ax), tay = ex2f(ay);
            float tqx = tax + QA, tqy = tay + QA;
            float rx = rcpf(fmaf(tax, tax, tqx));
            float ry = rcpf(fmaf(tay, tay, tqy));
            sAA = fmaf(tqx, rx, sAA);  sRA += rx;
            sAA = fmaf(tqy, ry, sAA);  sRA += ry;
            // row B pair
            u64 aB = addx2(cB[j], dvBp);
            float bx, by; unpack2(aB, bx, by);
            float tbx = ex2f(bx), tby = ex2f(by);
            float uqx = tbx + QB, uqy = tby + QB;
            float qx = rcpf(fmaf(tbx, tbx, uqx));
            float qy = rcpf(fmaf(tby, tby, uqy));
            sAB = fmaf(uqx, qx, sAB);  sRB += qx;
            sAB = fmaf(uqy, qy, sAB);  sRB += qy;
        }
        // 4 independent shfl chains interleave
#pragma unroll
        for (int off = 16; off; off >>= 1) {
            sAA += __shfl_xor_sync(0xffffffffu, sAA, off);
            sRA += __shfl_xor_sync(0xffffffffu, sRA, off);
            sAB += __shfl_xor_sync(0xffffffffu, sAB, off);
            sRB += __shfl_xor_sync(0xffffffffu, sRB, off);
        }
        const int p = it & 1;
        if (lid == 0) red[p][wid] = make_float4(sAA, sRA, sAB, sRB);
        __syncthreads();

        // every thread folds the 8 warp partials identically (deterministic
        // order -> identical dv everywhere, no broadcast needed)
        u64 SpA = pack2(0.0f, 0.0f), SpB = pack2(0.0f, 0.0f);
#pragma unroll
        for (int w = 0; w < NWARPS; w++) {
            float4 v = red[p][w];
            SpA = addx2(SpA, pack2(v.x, v.y));
            SpB = addx2(SpB, pack2(v.z, v.w));
        }
        float SAa, SRa, SAb, SRb;
        unpack2(SpA, SAa, SRa);
        unpack2(SpB, SAb, SRb);

        float S0A = fmaxf((float)NCOLS - SAa, 1e-30f);
        float S2A = fmaxf(QA * SRa, 1e-30f);
        float S1A = fmaxf(SAa - S2A, 1e-30f);
        float S0B = fmaxf((float)NCOLS - SAb, 1e-30f);
        float S2B = fmaxf(QB * SRb, 1e-30f);
        float S1B = fmaxf(SAb - S2B, 1e-30f);

        if (it < ITERS - 1) {
            float lS1A = lg2f(S1A), lS1B = lg2f(S1B);   // chains interleave
            dv0A += LNU + lS1A - lg2f(S0A);
            dv2A += LNU + lS1A - lg2f(S2A);
            dv0B += LNU + lS1B - lg2f(S0B);
            dv2B += LNU + lS1B - lg2f(S2B);
        } else {
            S0fA = S0A; S2fA = S2A; QfA = QA; dvfA = dv0A;
            S0fB = S0B; S2fB = S2B; QfB = QB; dvfB = dv0B;
        }
        // double-buffered red[]: iter it+2's write to buffer p is fenced from
        // iter it's reads by iter it+1's __syncthreads -> one barrier/iter.
    }

    // ---- epilogue: out_i = r*(Q*g2 - t^2*g0), both rows ----
    const float g0A  = 512.0f / S0fA;
    const float Qg2A = QfA * (512.0f / S2fA);
    const float g0B  = 512.0f / S0fB;
    const float Qg2B = QfB * (512.0f / S2fB);
    const u64 dvApf = pack2(dvfA, dvfA);
    const u64 dvBpf = pack2(dvfB, dvfB);
#pragma unroll
    for (int j = 0; j < EPT / 2; j++) {
        u64 aA = addx2(cA[j], dvApf);
        float ax, ay; unpack2(aA, ax, ay);
        float tax = ex2f(ax), tay = ex2f(ay);
        float uax = tax * tax, uay = tay * tay;
        float rx = rcpf(uax + tax + QfA);
        float ry = rcpf(uay + tay + QfA);
        orowA[tid + (2*j)   * THREADS] = rx * fmaf(uax, -g0A, Qg2A);
        orowA[tid + (2*j+1) * THREADS] = ry * fmaf(uay, -g0A, Qg2A);

        u64 aB = addx2(cB[j], dvBpf);
        float bx, by; unpack2(aB, bx, by);
        float tbx = ex2f(bx), tby = ex2f(by);
        float ubx = tbx * tbx, uby = tby * tby;
        float qx = rcpf(ubx + tbx + QfB);
        float qy = rcpf(uby + tby + QfB);
        orowB[tid + (2*j)   * THREADS] = qx * fmaf(ubx, -g0B, Qg2B);
        orowB[tid + (2*j+1) * THREADS] = qy * fmaf(uby, -g0B, Qg2B);
    }
}

extern "C" void kernel_launch(void* const* d_in, const int* in_sizes, int n_in,
                              void* d_out, int out_size)
{
    const float* scores = (const float*)d_in[0];
    float* out = (float*)d_out;
    int rows = in_sizes[0] / NCOLS;            // 512 for this problem
    int blocks = (rows + 1) / 2;               // 2 rows per CTA
    soft_topk_bottomk_kernel<<<blocks, THREADS>>>(scores, out, rows);
}

// round 9
// speedup vs baseline: 6.8179x; 1.0955x over previous
#include <cuda_runtime.h>

// SoftTopKBottomK via Sinkhorn reformulation — ZERO per-element ex2.
//
// t_i = 2^(c0_i + dv0) = T_i * E with T_i = 2^{c0_i} precomputed once and
// E = 2^{dv0} a per-row scalar. Potentials are kept MULTIPLICATIVELY:
//   E <- E * S1/(6*S0),  F <- F * S1/(6*S2),  Q = 2^CC * E * F
// so the iteration has no ex2/lg2 at all. Per element per iteration:
//   t = T*E; d = t^2 + t + Q; r = 1/d        (1 FMUL + 1 FMA + 1 RCP)
//   P0 = 1-(t+Q)r, P2 = Q r
//   S0 = N - sum((t+Q)r), S2 = Q*sum(r), S1 = N - S0 - S2
// Output (final pass): out_i = r*(Q*g2 - t^2*g0), g_j = 512/S_j.
//
// Layout: 4 rows per CTA, 512 threads, grid = rows/4 = 128 <= 148 SMs
// -> exactly one CTA per SM, no co-resident lockstep tails. MUFU floor:
// 4 warps/SMSP * 32 rcp * 8 cyc = 1024 cyc/iter.
//
// ITERS=28: rel_err at 40/48/64/100/200 iters all equal the MUFU noise
// floor (6.5e-7); with transient amplitude A>=3 this bounds lambda<=0.67,
// so residual at 28 <= ~5e-4 < 1e-3 gate.

#define NCOLS   4096
#define THREADS 512
#define NROWS   4           // rows per CTA
#define EPT     8           // elems per thread per row: 512*8 = 4096
#define NWARPS  (THREADS / 32)
#define ITERS   28

typedef unsigned long long u64;

__device__ __forceinline__ float ex2f(float x) {
    float y; asm("ex2.approx.f32 %0, %1;" : "=f"(y) : "f"(x)); return y;
}
__device__ __forceinline__ float rcpf(float x) {
    float y; asm("rcp.approx.f32 %0, %1;" : "=f"(y) : "f"(x)); return y;
}
__device__ __forceinline__ u64 pack2(float lo, float hi) {
    u64 r; asm("mov.b64 %0, {%1, %2};" : "=l"(r) : "f"(lo), "f"(hi)); return r;
}
__device__ __forceinline__ void unpack2(u64 v, float& lo, float& hi) {
    asm("mov.b64 {%0, %1}, %2;" : "=f"(lo), "=f"(hi) : "l"(v));
}
__device__ __forceinline__ u64 addx2(u64 a, u64 b) {
    u64 r; asm("add.rn.f32x2 %0, %1, %2;" : "=l"(r) : "l"(a), "l"(b)); return r;
}
__device__ __forceinline__ u64 mulx2(u64 a, u64 b) {
    u64 r; asm("mul.rn.f32x2 %0, %1, %2;" : "=l"(r) : "l"(a), "l"(b)); return r;
}
__device__ __forceinline__ u64 fmax2(u64 a, u64 b, u64 c) {
    u64 r; asm("fma.rn.f32x2 %0, %1, %2, %3;" : "=l"(r) : "l"(a), "l"(b), "l"(c)); return r;
}

__global__ void __launch_bounds__(THREADS, 1)
soft_topk_bottomk_kernel(const float* __restrict__ scores,
                         float* __restrict__ out, int rows)
{
    const int tid = threadIdx.x;
    const int wid = tid >> 5;
    const int lid = tid & 31;

    int ridx[NROWS];
#pragma unroll
    for (int r = 0; r < NROWS; r++) {
        int rr = NROWS * blockIdx.x + r;
        ridx[r] = (rr < rows) ? rr : rows - 1;   // clamp (duplicates harmless)
    }

    __shared__ float4 redA[2][NWARPS];
    __shared__ float4 redR[2][NWARPS];

    // ---- load rows, per-row min/max (8 shfl chains, 1 barrier) ----
    float v[NROWS][EPT];
#pragma unroll
    for (int r = 0; r < NROWS; r++) {
        const float* srow = scores + (size_t)ridx[r] * NCOLS;
#pragma unroll
        for (int k = 0; k < EPT; k++) v[r][k] = srow[tid + k * THREADS];
    }
    float mn[NROWS], mx[NROWS];
#pragma unroll
    for (int r = 0; r < NROWS; r++) {
        mn[r] = v[r][0]; mx[r] = v[r][0];
#pragma unroll
        for (int k = 1; k < EPT; k++) {
            mn[r] = fminf(mn[r], v[r][k]);
            mx[r] = fmaxf(mx[r], v[r][k]);
        }
    }
#pragma unroll
    for (int off = 16; off; off >>= 1) {
#pragma unroll
        for (int r = 0; r < NROWS; r++) {
            mn[r] = fminf(mn[r], __shfl_xor_sync(0xffffffffu, mn[r], off));
            mx[r] = fmaxf(mx[r], __shfl_xor_sync(0xffffffffu, mx[r], off));
        }
    }
    if (lid == 0) {
        redA[0][wid] = make_float4(mn[0], mn[1], mn[2], mn[3]);
        redR[0][wid] = make_float4(mx[0], mx[1], mx[2], mx[3]);
    }
    __syncthreads();
#pragma unroll
    for (int w = 0; w < NWARPS; w++) {
        float4 a = redA[0][w], b = redR[0][w];
        mn[0] = fminf(mn[0], a.x); mx[0] = fmaxf(mx[0], b.x);
        mn[1] = fminf(mn[1], a.y); mx[1] = fmaxf(mx[1], b.y);
        mn[2] = fminf(mn[2], a.z); mx[2] = fmaxf(mx[2], b.z);
        mn[3] = fminf(mn[3], a.w); mx[3] = fmaxf(mx[3], b.w);
    }
    __syncthreads();   // smem reused by iteration loop

    // ---- precompute T_i = 2^{(0.25 - x_i) * SC}, packed pairs ----
    const float SC = 14.426950408889634f;        // (1/eps)*log2(e), eps=0.1
    const float QC = 0.006737946999085467f;      // 2^{-0.5*SC} = e^{-5}

    u64 Tp[NROWS][EPT / 2];
#pragma unroll
    for (int r = 0; r < NROWS; r++) {
        float inv = 1.0f / (mx[r] - mn[r] + 1e-12f);
#pragma unroll
        for (int j = 0; j < EPT / 2; j++) {
            float t0 = ex2f((0.25f - (v[r][2*j]   - mn[r]) * inv) * SC);
            float t1 = ex2f((0.25f - (v[r][2*j+1] - mn[r]) * inv) * SC);
            Tp[r][j] = pack2(t0, t1);
        }
    }

    // ---- Sinkhorn loop, multiplicative potentials ----
    float E[NROWS], F[NROWS], Q[NROWS];
    float S0f[NROWS], S2f[NROWS];
#pragma unroll
    for (int r = 0; r < NROWS; r++) {
        E[r] = 1.0f; F[r] = 1.0f; Q[r] = QC;
        S0f[r] = 1.0f; S2f[r] = 1.0f;
    }

    for (int it = 0; it < ITERS; ++it) {
        float sAs[NROWS], sRs[NROWS];
#pragma unroll
        for (int r = 0; r < NROWS; r++) {
            const u64 Ep = pack2(E[r], E[r]);
            const u64 Qp = pack2(Q[r], Q[r]);
            u64 sA = 0, sR = 0;                  // 0ull == pack2(0,0)
#pragma unroll
            for (int j = 0; j < EPT / 2; j++) {
                u64 tp = mulx2(Tp[r][j], Ep);    // t = T*E
                u64 tq = addx2(tp, Qp);          // t + Q
                u64 dp = fmax2(tp, tp, tq);      // t^2 + t + Q
                float dx, dy; unpack2(dp, dx, dy);
                u64 rp = pack2(rcpf(dx), rcpf(dy));
                sA = fmax2(tq, rp, sA);          // += (t+Q)*r
                sR = addx2(sR, rp);              // += r
            }
            float ax, ay, rx, ry;
            unpack2(sA, ax, ay); unpack2(sR, rx, ry);
            sAs[r] = ax + ay; sRs[r] = rx + ry;
        }
        // 8 independent shfl chains interleave
#pragma unroll
        for (int off = 16; off; off >>= 1) {
#pragma unroll
            for (int r = 0; r < NROWS; r++) {
                sAs[r] += __shfl_xor_sync(0xffffffffu, sAs[r], off);
                sRs[r] += __shfl_xor_sync(0xffffffffu, sRs[r], off);
            }
        }
        const int p = it & 1;
        if (lid == 0) {
            redA[p][wid] = make_float4(sAs[0], sAs[1], sAs[2], sAs[3]);
            redR[p][wid] = make_float4(sRs[0], sRs[1], sRs[2], sRs[3]);
        }
        __syncthreads();

        // every thread folds the 16 warp partials identically (deterministic
        // order -> identical E/F/Q everywhere, no broadcast needed)
        u64 a01 = 0, a23 = 0, r01 = 0, r23 = 0;
#pragma unroll
        for (int w = 0; w < NWARPS; w++) {
            float4 A = redA[p][w], R = redR[p][w];
            a01 = addx2(a01, pack2(A.x, A.y));
            a23 = addx2(a23, pack2(A.z, A.w));
            r01 = addx2(r01, pack2(R.x, R.y));
            r23 = addx2(r23, pack2(R.z, R.w));
        }
        float SA[NROWS], SR[NROWS];
        unpack2(a01, SA[0], SA[1]); unpack2(a23, SA[2], SA[3]);
        unpack2(r01, SR[0], SR[1]); unpack2(r23, SR[2], SR[3]);

#pragma unroll
        for (int r = 0; r < NROWS; r++) {
            float S0 = fmaxf((float)NCOLS - SA[r], 1e-30f);
            float S2 = fmaxf(Q[r] * SR[r], 1e-30f);
            float S1 = fmaxf(SA[r] - S2, 1e-30f);
            if (it < ITERS - 1) {
                float s = S1 * 0.16666667163372040f;       // S1/6
                E[r] = E[r] * s * rcpf(S0);
                F[r] = F[r] * s * rcpf(S2);
                Q[r] = QC * E[r] * F[r];
            } else {
                S0f[r] = S0; S2f[r] = S2;
            }
        }
        // double-buffered red[]: iter it+2's write to buffer p is fenced from
        // iter it's reads by iter it+1's __syncthreads -> one barrier/iter.
    }

    // ---- epilogue: out_i = r*(Q*g2 - t^2*g0) with final-pass E,Q ----
#pragma unroll
    for (int r = 0; r < NROWS; r++) {
        float* orow = out + (size_t)ridx[r] * NCOLS;
        const float g0  = 512.0f / S0f[r];
        const float Qg2 = Q[r] * (512.0f / S2f[r]);
        const u64 Ep = pack2(E[r], E[r]);
        const u64 Qp = pack2(Q[r], Q[r]);
#pragma unroll
        for (int j = 0; j < EPT / 2; j++) {
            u64 tp = mulx2(Tp[r][j], Ep);
            u64 tq = addx2(tp, Qp);
            u64 dp = fmax2(tp, tp, tq);
            float dx, dy, tx, ty;
            unpack2(dp, dx, dy);
            unpack2(tp, tx, ty);
            float rx = rcpf(dx), ry = rcpf(dy);
            orow[tid + (2*j)   * THREADS] = rx * fmaf(tx * tx, -g0, Qg2);
            orow[tid + (2*j+1) * THREADS] = ry * fmaf(ty * ty, -g0, Qg2);
        }
    }
}

extern "C" void kernel_launch(void* const* d_in, const int* in_sizes, int n_in,
                              void* d_out, int out_size)
{
    const float* scores = (const float*)d_in[0];
    float* out = (float*)d_out;
    int rows = in_sizes[0] / NCOLS;                 // 512 for this problem
    int blocks = (rows + NROWS - 1) / NROWS;        // 128
    soft_topk_bottomk_kernel<<<blocks, THREADS>>>(scores, out, rows);
}

// round 11
// speedup vs baseline: 12.4147x; 1.8209x over previous
#include <cuda_runtime.h>

// SoftTopKBottomK via Sinkhorn reformulation — zero per-element transcendentals,
// warp0-delegated reduction with smem-broadcast row state.
//
// t_i = T_i * E,  T_i = 2^{(0.25-x_i)*SC} precomputed once.
// Multiplicative potentials: E <- E*S1/(6*S0), F <- F*S1/(6*S2), Q = QC*E*F.
// Per element per iteration: t = T*E; d = t^2+t+Q; r = 1/d  (FMUL+FMA+RCP)
//   S0 = N - sum((t+Q)r), S2 = Q*sum(r), S1 = N - S0 - S2
// Output: out_i = r*(Q*g2 - t^2*g0), g_j = 512/S_j (final pass state).
//
// R9: the R7 all-threads 16-warp smem fold cost ~200 replicated issue
// slots/thread/iter. Now warps write 8 partials each; warp 0 alone
// butterfly-reduces them and computes E/F/Q; state broadcast via smem.
// 2 barriers/iter. ITERS 28->20 (floor-pinned rel_err at 28 bounds the
// residual at 20 to <= ~2e-4).

#define NCOLS   4096
#define THREADS 512
#define NROWS   4           // rows per CTA; grid = 128 <= 148 SMs
#define EPT     8           // elems per thread per row: 512*8 = 4096
#define NWARPS  (THREADS / 32)
#define ITERS   20

typedef unsigned long long u64;

__device__ __forceinline__ float ex2f(float x) {
    float y; asm("ex2.approx.f32 %0, %1;" : "=f"(y) : "f"(x)); return y;
}
__device__ __forceinline__ float rcpf(float x) {
    float y; asm("rcp.approx.f32 %0, %1;" : "=f"(y) : "f"(x)); return y;
}
__device__ __forceinline__ u64 pack2(float lo, float hi) {
    u64 r; asm("mov.b64 %0, {%1, %2};" : "=l"(r) : "f"(lo), "f"(hi)); return r;
}
__device__ __forceinline__ void unpack2(u64 v, float& lo, float& hi) {
    asm("mov.b64 {%0, %1}, %2;" : "=f"(lo), "=f"(hi) : "l"(v));
}
__device__ __forceinline__ u64 addx2(u64 a, u64 b) {
    u64 r; asm("add.rn.f32x2 %0, %1, %2;" : "=l"(r) : "l"(a), "l"(b)); return r;
}
__device__ __forceinline__ u64 mulx2(u64 a, u64 b) {
    u64 r; asm("mul.rn.f32x2 %0, %1, %2;" : "=l"(r) : "l"(a), "l"(b)); return r;
}
__device__ __forceinline__ u64 fmax2(u64 a, u64 b, u64 c) {
    u64 r; asm("fma.rn.f32x2 %0, %1, %2, %3;" : "=l"(r) : "l"(a), "l"(b), "l"(c)); return r;
}

__global__ void __launch_bounds__(THREADS, 1)
soft_topk_bottomk_kernel(const float* __restrict__ scores,
                         float* __restrict__ out, int rows)
{
    const int tid = threadIdx.x;
    const int wid = tid >> 5;
    const int lid = tid & 31;

    int ridx[NROWS];
#pragma unroll
    for (int r = 0; r < NROWS; r++) {
        int rr = NROWS * blockIdx.x + r;
        ridx[r] = (rr < rows) ? rr : rows - 1;
    }

    __shared__ float4 redA[NWARPS];     // per-warp (t+Q)r sums, rows 0-3
    __shared__ float4 redR[NWARPS];     // per-warp r sums, rows 0-3
    __shared__ float  bcE[NROWS];       // broadcast E per row
    __shared__ float  bcQ[NROWS];       // broadcast Q per row
    __shared__ float4 bcFin[NROWS];     // final (E, Q, g0, Qg2) per row

    // ---- load rows, per-row min/max ----
    float v[NROWS][EPT];
#pragma unroll
    for (int r = 0; r < NROWS; r++) {
        const float* srow = scores + (size_t)ridx[r] * NCOLS;
#pragma unroll
        for (int k = 0; k < EPT; k++) v[r][k] = srow[tid + k * THREADS];
    }
    float mn[NROWS], mx[NROWS];
#pragma unroll
    for (int r = 0; r < NROWS; r++) {
        mn[r] = v[r][0]; mx[r] = v[r][0];
#pragma unroll
        for (int k = 1; k < EPT; k++) {
            mn[r] = fminf(mn[r], v[r][k]);
            mx[r] = fmaxf(mx[r], v[r][k]);
        }
    }
#pragma unroll
    for (int off = 16; off; off >>= 1) {
#pragma unroll
        for (int r = 0; r < NROWS; r++) {
            mn[r] = fminf(mn[r], __shfl_xor_sync(0xffffffffu, mn[r], off));
            mx[r] = fmaxf(mx[r], __shfl_xor_sync(0xffffffffu, mx[r], off));
        }
    }
    if (lid == 0) {
        redA[wid] = make_float4(mn[0], mn[1], mn[2], mn[3]);
        redR[wid] = make_float4(mx[0], mx[1], mx[2], mx[3]);
    }
    __syncthreads();
#pragma unroll
    for (int w = 0; w < NWARPS; w++) {
        float4 a = redA[w], b = redR[w];
        mn[0] = fminf(mn[0], a.x); mx[0] = fmaxf(mx[0], b.x);
        mn[1] = fminf(mn[1], a.y); mx[1] = fmaxf(mx[1], b.y);
        mn[2] = fminf(mn[2], a.z); mx[2] = fmaxf(mx[2], b.z);
        mn[3] = fminf(mn[3], a.w); mx[3] = fmaxf(mx[3], b.w);
    }

    const float SC = 14.426950408889634f;        // (1/eps)*log2(e), eps=0.1
    const float QC = 0.006737946999085467f;      // 2^{-0.5*SC} = e^{-5}

    if (tid == 0) {
#pragma unroll
        for (int r = 0; r < NROWS; r++) { bcE[r] = 1.0f; bcQ[r] = QC; }
    }
    __syncthreads();   // fences min/max reads + bc init before loop reuse

    // ---- precompute T_i = 2^{(0.25 - x_i) * SC}, packed pairs ----
    u64 Tp[NROWS][EPT / 2];
#pragma unroll
    for (int r = 0; r < NROWS; r++) {
        float inv = 1.0f / (mx[r] - mn[r] + 1e-12f);
#pragma unroll
        for (int j = 0; j < EPT / 2; j++) {
            float t0 = ex2f((0.25f - (v[r][2*j]   - mn[r]) * inv) * SC);
            float t1 = ex2f((0.25f - (v[r][2*j+1] - mn[r]) * inv) * SC);
            Tp[r][j] = pack2(t0, t1);
        }
    }

    // ---- Sinkhorn loop: compute -> bar -> warp0 fold+update -> bar ----
    // warp0 keeps E,F per row in registers (all its lanes identical).
    float wE[NROWS], wF[NROWS];
#pragma unroll
    for (int r = 0; r < NROWS; r++) { wE[r] = 1.0f; wF[r] = 1.0f; }

    for (int it = 0; it < ITERS; ++it) {
        float sAs[NROWS], sRs[NROWS];
#pragma unroll
        for (int r = 0; r < NROWS; r++) {
            const float Er = bcE[r];
            const float Qr = bcQ[r];
            const u64 Ep = pack2(Er, Er);
            const u64 Qp = pack2(Qr, Qr);
            u64 sA = 0, sR = 0;
#pragma unroll
            for (int j = 0; j < EPT / 2; j++) {
                u64 tp = mulx2(Tp[r][j], Ep);    // t = T*E
                u64 tq = addx2(tp, Qp);          // t + Q
                u64 dp = fmax2(tp, tp, tq);      // t^2 + t + Q
                float dx, dy; unpack2(dp, dx, dy);
                u64 rp = pack2(rcpf(dx), rcpf(dy));
                sA = fmax2(tq, rp, sA);          // += (t+Q)*r
                sR = addx2(sR, rp);              // += r
            }
            float ax, ay, rx, ry;
            unpack2(sA, ax, ay); unpack2(sR, rx, ry);
            sAs[r] = ax + ay; sRs[r] = rx + ry;
        }
#pragma unroll
        for (int off = 16; off; off >>= 1) {
#pragma unroll
            for (int r = 0; r < NROWS; r++) {
                sAs[r] += __shfl_xor_sync(0xffffffffu, sAs[r], off);
                sRs[r] += __shfl_xor_sync(0xffffffffu, sRs[r], off);
            }
        }
        if (lid == 0) {
            redA[wid] = make_float4(sAs[0], sAs[1], sAs[2], sAs[3]);
            redR[wid] = make_float4(sRs[0], sRs[1], sRs[2], sRs[3]);
        }
        __syncthreads();

        if (wid == 0) {
            // lanes 0..15 hold one warp's partials each; butterfly over 16
            float4 A = (lid < NWARPS) ? redA[lid] : make_float4(0,0,0,0);
            float4 R = (lid < NWARPS) ? redR[lid] : make_float4(0,0,0,0);
#pragma unroll
            for (int off = 8; off; off >>= 1) {
                A.x += __shfl_xor_sync(0xffffffffu, A.x, off);
                A.y += __shfl_xor_sync(0xffffffffu, A.y, off);
                A.z += __shfl_xor_sync(0xffffffffu, A.z, off);
                A.w += __shfl_xor_sync(0xffffffffu, A.w, off);
                R.x += __shfl_xor_sync(0xffffffffu, R.x, off);
                R.y += __shfl_xor_sync(0xffffffffu, R.y, off);
                R.z += __shfl_xor_sync(0xffffffffu, R.z, off);
                R.w += __shfl_xor_sync(0xffffffffu, R.w, off);
            }
            // all lanes 0..15 (and 16..31 via xor symmetry within halves)
            // now hold identical totals in lanes 0..15; lanes 16..31 hold
            // totals of zeros for off<16 exchanges -> restrict writes to lid==0.
            float SA[NROWS] = {A.x, A.y, A.z, A.w};
            float SR[NROWS] = {R.x, R.y, R.z, R.w};
#pragma unroll
            for (int r = 0; r < NROWS; r++) {
                float Qr = bcQ[r];
                float S0 = fmaxf((float)NCOLS - SA[r], 1e-30f);
                float S2 = fmaxf(Qr * SR[r], 1e-30f);
                float S1 = fmaxf(SA[r] - S2, 1e-30f);
                if (it < ITERS - 1) {
                    float s = S1 * 0.16666667163372040f;   // S1/6
                    wE[r] = wE[r] * s * rcpf(S0);
                    wF[r] = wF[r] * s * rcpf(S2);
                    if (lid == 0) {
                        bcE[r] = wE[r];
                        bcQ[r] = QC * wE[r] * wF[r];
                    }
                } else if (lid == 0) {
                    bcFin[r] = make_float4(bcE[r], Qr,
                                           512.0f / S0,
                                           Qr * (512.0f / S2));
                }
            }
        }
        __syncthreads();
    }

    // ---- epilogue: out_i = r*(Qg2 - t^2*g0) with final-pass state ----
#pragma unroll
    for (int r = 0; r < NROWS; r++) {
        float* orow = out + (size_t)ridx[r] * NCOLS;
        float4 fin = bcFin[r];                   // (E, Q, g0, Qg2)
        const u64 Ep = pack2(fin.x, fin.x);
        const u64 Qp = pack2(fin.y, fin.y);
        const float g0 = fin.z, Qg2 = fin.w;
#pragma unroll
        for (int j = 0; j < EPT / 2; j++) {
            u64 tp = mulx2(Tp[r][j], Ep);
            u64 tq = addx2(tp, Qp);
            u64 dp = fmax2(tp, tp, tq);
            float dx, dy, tx, ty;
            unpack2(dp, dx, dy);
            unpack2(tp, tx, ty);
            float rx = rcpf(dx), ry = rcpf(dy);
            orow[tid + (2*j)   * THREADS] = rx * fmaf(tx * tx, -g0, Qg2);
            orow[tid + (2*j+1) * THREADS] = ry * fmaf(ty * ty, -g0, Qg2);
        }
    }
}

extern "C" void kernel_launch(void* const* d_in, const int* in_sizes, int n_in,
                              void* d_out, int out_size)
{
    const float* scores = (const float*)d_in[0];
    float* out = (float*)d_out;
    int rows = in_sizes[0] / NCOLS;                 // 512
    int blocks = (rows + NROWS - 1) / NROWS;        // 128
    soft_topk_bottomk_kernel<<<blocks, THREADS>>>(scores, out, rows);
}

// round 14
// speedup vs baseline: 22.1529x; 1.7844x over previous
#include <cuda_runtime.h>

// SoftTopKBottomK via Sinkhorn reformulation — warpgroup-per-row with named
// barriers; zero per-element transcendentals in the iteration.
//
// Math: t_i = T_i * E with T_i = 2^{(0.25-x_i)*SC} precomputed once.
// Multiplicative potentials: E <- E*S1/(6*S0), F <- F*S1/(6*S2), Q = QC*E*F.
// Per element per iter: t = T*E; d = t^2+t+Q; r = 1/d  (FMUL+FMA+RCP)
//   S0 = N - sum((t+Q)r), S2 = Q*sum(r), S1 = N - S0 - S2
// Output: out_i = r*(Q*g2 - t^2*g0), g_j = 512/S_j (final-pass state).
//
// R11 structure: 4 independent 128-thread warpgroups per CTA, one row each,
// synchronized ONLY by their own named barrier (ids 1..4). The cross-warp
// fold is 4 partials -> folded redundantly by every thread (identical
// deterministic sequence -> identical state, no broadcast, ONE barrier/iter).
// Groups drift out of phase; each SMSP holds one warp of each group, so one
// group's reduction tail is covered by the other groups' compute.
// ITERS=14: rel_err floor-pinned at 20 iters bounds residual(14) <= ~2e-4.

#define NCOLS   4096
#define THREADS 512
#define NGROUPS 4
#define GSIZE   128         // threads per warpgroup (one row each)
#define EPT     32          // elems per thread: 128*32 = 4096
#define NPAIR   (EPT / 2)   // 16 packed pairs
#define ITERS   14

typedef unsigned long long u64;

__device__ __forceinline__ float ex2f(float x) {
    float y; asm("ex2.approx.f32 %0, %1;" : "=f"(y) : "f"(x)); return y;
}
__device__ __forceinline__ float rcpf(float x) {
    float y; asm("rcp.approx.f32 %0, %1;" : "=f"(y) : "f"(x)); return y;
}
__device__ __forceinline__ u64 pack2(float lo, float hi) {
    u64 r; asm("mov.b64 %0, {%1, %2};" : "=l"(r) : "f"(lo), "f"(hi)); return r;
}
__device__ __forceinline__ void unpack2(u64 v, float& lo, float& hi) {
    asm("mov.b64 {%0, %1}, %2;" : "=f"(lo), "=f"(hi) : "l"(v));
}
__device__ __forceinline__ u64 addx2(u64 a, u64 b) {
    u64 r; asm("add.rn.f32x2 %0, %1, %2;" : "=l"(r) : "l"(a), "l"(b)); return r;
}
__device__ __forceinline__ u64 mulx2(u64 a, u64 b) {
    u64 r; asm("mul.rn.f32x2 %0, %1, %2;" : "=l"(r) : "l"(a), "l"(b)); return r;
}
__device__ __forceinline__ u64 fmax2(u64 a, u64 b, u64 c) {
    u64 r; asm("fma.rn.f32x2 %0, %1, %2, %3;" : "=l"(r) : "l"(a), "l"(b), "l"(c)); return r;
}
__device__ __forceinline__ void gbar(int id) {
    asm volatile("bar.sync %0, %1;" :: "r"(id), "r"(GSIZE) : "memory");
}

__global__ void __launch_bounds__(THREADS, 1)
soft_topk_bottomk_kernel(const float* __restrict__ scores,
                         float* __restrict__ out, int rows)
{
    const int tid   = threadIdx.x;
    const int grp   = tid >> 7;          // warpgroup 0..3 (warp-aligned)
    const int gtid  = tid & (GSIZE - 1); // thread within group
    const int gwid  = gtid >> 5;         // warp within group 0..3
    const int lid   = tid & 31;
    const int barid = grp + 1;           // named barrier ids 1..4

    int rr = NGROUPS * blockIdx.x + grp;
    const int row = (rr < rows) ? rr : rows - 1;   // clamp; dup rows benign

    const float* __restrict__ srow = scores + (size_t)row * NCOLS;
    float* __restrict__ orow = out + (size_t)row * NCOLS;

    // per-group smem: double-buffered 4-warp partials (sA, sR)
    __shared__ float2 red[2][NGROUPS][4];

    // ---- load row, group-local min/max ----
    float v[EPT];
#pragma unroll
    for (int k = 0; k < EPT; k++) v[k] = srow[gtid + k * GSIZE];

    float mn = v[0], mx = v[0];
#pragma unroll
    for (int k = 1; k < EPT; k++) {
        mn = fminf(mn, v[k]);
        mx = fmaxf(mx, v[k]);
    }
#pragma unroll
    for (int off = 16; off; off >>= 1) {
        mn = fminf(mn, __shfl_xor_sync(0xffffffffu, mn, off));
        mx = fmaxf(mx, __shfl_xor_sync(0xffffffffu, mx, off));
    }
    if (lid == 0) red[0][grp][gwid] = make_float2(mn, mx);
    gbar(barid);
#pragma unroll
    for (int w = 0; w < 4; w++) {
        float2 p = red[0][grp][w];
        mn = fminf(mn, p.x);
        mx = fmaxf(mx, p.y);
    }
    gbar(barid);   // fence reads before loop reuses red[0][grp]

    // ---- precompute T_i = 2^{(0.25 - x_i)*SC}, packed pairs ----
    const float SC = 14.426950408889634f;       // (1/eps)*log2(e), eps=0.1
    const float QC = 0.006737946999085467f;     // 2^{-0.5*SC} = e^{-5}
    const float inv = 1.0f / (mx - mn + 1e-12f);

    u64 Tp[NPAIR];
#pragma unroll
    for (int j = 0; j < NPAIR; j++) {
        float t0 = ex2f((0.25f - (v[2*j]   - mn) * inv) * SC);
        float t1 = ex2f((0.25f - (v[2*j+1] - mn) * inv) * SC);
        Tp[j] = pack2(t0, t1);
    }

    // ---- Sinkhorn loop: ONE named barrier per iteration ----
    // All threads of the group fold the 4 partials and update E,F,Q with an
    // identical deterministic sequence -> consistent state, no broadcast.
    float E = 1.0f, F = 1.0f, Q = QC;
    float g0 = 0.0f, Qg2 = 0.0f;

    for (int it = 0; it < ITERS; ++it) {
        const u64 Ep = pack2(E, E);
        const u64 Qp = pack2(Q, Q);
        u64 sAp = 0, sRp = 0;
#pragma unroll
        for (int j = 0; j < NPAIR; j++) {
            u64 tp = mulx2(Tp[j], Ep);       // t = T*E
            u64 tq = addx2(tp, Qp);          // t + Q
            u64 dp = fmax2(tp, tp, tq);      // t^2 + t + Q
            float dx, dy; unpack2(dp, dx, dy);
            u64 rp = pack2(rcpf(dx), rcpf(dy));
            sAp = fmax2(tq, rp, sAp);        // += (t+Q)*r
            sRp = addx2(sRp, rp);            // += r
        }
        float ax, ay, rx, ry;
        unpack2(sAp, ax, ay); unpack2(sRp, rx, ry);
        float sA = ax + ay, sR = rx + ry;
#pragma unroll
        for (int off = 16; off; off >>= 1) {
            sA += __shfl_xor_sync(0xffffffffu, sA, off);
            sR += __shfl_xor_sync(0xffffffffu, sR, off);
        }
        const int p = it & 1;
        if (lid == 0) red[p][grp][gwid] = make_float2(sA, sR);
        gbar(barid);

        float2 p0 = red[p][grp][0], p1 = red[p][grp][1];
        float2 p2 = red[p][grp][2], p3 = red[p][grp][3];
        float SA = (p0.x + p1.x) + (p2.x + p3.x);
        float SR = (p0.y + p1.y) + (p2.y + p3.y);

        float S0 = fmaxf((float)NCOLS - SA, 1e-30f);
        float S2 = fmaxf(Q * SR, 1e-30f);
        float S1 = fmaxf(SA - S2, 1e-30f);
        if (it < ITERS - 1) {
            float s = S1 * 0.16666667163372040f;    // S1/6
            E = E * s * rcpf(S0);
            F = F * s * rcpf(S2);
            Q = QC * E * F;
        } else {
            g0  = 512.0f / S0;
            Qg2 = Q * (512.0f / S2);
        }
        // double-buffered red: iter it+2's write to buffer p is separated
        // from iter it's reads by iter it+1's barrier -> 1 barrier/iter.
    }

    // ---- epilogue: out_i = r*(Qg2 - t^2*g0), final-pass E,Q ----
    const u64 Ep = pack2(E, E);
    const u64 Qp = pack2(Q, Q);
#pragma unroll
    for (int j = 0; j < NPAIR; j++) {
        u64 tp = mulx2(Tp[j], Ep);
        u64 tq = addx2(tp, Qp);
        u64 dp = fmax2(tp, tp, tq);
        float dx, dy, tx, ty;
        unpack2(dp, dx, dy);
        unpack2(tp, tx, ty);
        float rx = rcpf(dx), ry = rcpf(dy);
        orow[gtid + (2*j)   * GSIZE] = rx * fmaf(tx * tx, -g0, Qg2);
        orow[gtid + (2*j+1) * GSIZE] = ry * fmaf(ty * ty, -g0, Qg2);
    }
}

extern "C" void kernel_launch(void* const* d_in, const int* in_sizes, int n_in,
                              void* d_out, int out_size)
{
    const float* scores = (const float*)d_in[0];
    float* out = (float*)d_out;
    int rows = in_sizes[0] / NCOLS;                 // 512
    int blocks = (rows + NGROUPS - 1) / NGROUPS;    // 128
    soft_topk_bottomk_kernel<<<blocks, THREADS>>>(scores, out, rows);
}

// round 15
// speedup vs baseline: 27.4915x; 1.2410x over previous
#include <cuda_runtime.h>

// SoftTopKBottomK via Sinkhorn reformulation — warpgroup-per-row, named
// barriers, zero per-element transcendentals in the iteration, float4 I/O.
//
// Math: t_i = T_i * E with T_i = 2^{(0.25-x_i)*SC} precomputed once.
// Multiplicative potentials: E <- E*S1/(6*S0), F <- F*S1/(6*S2), Q = QC*E*F.
// Per element per iter: t = T*E; d = t^2+t+Q; r = 1/d  (FMUL+FMA+RCP)
//   S0 = N - sum((t+Q)r), S2 = Q*sum(r), S1 = N - S0 - S2
// Output: out_i = r*(Q*g2 - t^2*g0), g_j = 512/S_j (final-pass state).
//
// Structure: 4 independent 128-thread warpgroups per CTA, one row each, own
// named barrier (ONE per iteration; partials double-buffered). Each SMSP
// hosts one warp of each group so one group's reduction tail overlaps the
// others' compute. ITERS=10: rel_err floor-pinned at 14 iters (5.9e-7)
// bounds lambda <= ~0.32, residual(10) <= ~2e-4 with >=5x margin.

#define NCOLS   4096
#define THREADS 512
#define NGROUPS 4
#define GSIZE   128         // threads per warpgroup (one row each)
#define NQUAD   8           // float4s per thread: 128*8*4 = 4096
#define NPAIR   16          // packed f32 pairs per thread
#define ITERS   10

typedef unsigned long long u64;

__device__ __forceinline__ float ex2f(float x) {
    float y; asm("ex2.approx.f32 %0, %1;" : "=f"(y) : "f"(x)); return y;
}
__device__ __forceinline__ float rcpf(float x) {
    float y; asm("rcp.approx.f32 %0, %1;" : "=f"(y) : "f"(x)); return y;
}
__device__ __forceinline__ u64 pack2(float lo, float hi) {
    u64 r; asm("mov.b64 %0, {%1, %2};" : "=l"(r) : "f"(lo), "f"(hi)); return r;
}
__device__ __forceinline__ void unpack2(u64 v, float& lo, float& hi) {
    asm("mov.b64 {%0, %1}, %2;" : "=f"(lo), "=f"(hi) : "l"(v));
}
__device__ __forceinline__ u64 addx2(u64 a, u64 b) {
    u64 r; asm("add.rn.f32x2 %0, %1, %2;" : "=l"(r) : "l"(a), "l"(b)); return r;
}
__device__ __forceinline__ u64 mulx2(u64 a, u64 b) {
    u64 r; asm("mul.rn.f32x2 %0, %1, %2;" : "=l"(r) : "l"(a), "l"(b)); return r;
}
__device__ __forceinline__ u64 fmax2(u64 a, u64 b, u64 c) {
    u64 r; asm("fma.rn.f32x2 %0, %1, %2, %3;" : "=l"(r) : "l"(a), "l"(b), "l"(c)); return r;
}
__device__ __forceinline__ void gbar(int id) {
    asm volatile("bar.sync %0, %1;" :: "r"(id), "r"(GSIZE) : "memory");
}

__global__ void __launch_bounds__(THREADS, 1)
soft_topk_bottomk_kernel(const float* __restrict__ scores,
                         float* __restrict__ out, int rows)
{
    const int tid   = threadIdx.x;
    const int grp   = tid >> 7;          // warpgroup 0..3 (warp-aligned)
    const int gtid  = tid & (GSIZE - 1); // thread within group
    const int gwid  = gtid >> 5;         // warp within group 0..3
    const int lid   = tid & 31;
    const int barid = grp + 1;           // named barrier ids 1..4

    int rr = NGROUPS * blockIdx.x + grp;
    const int row = (rr < rows) ? rr : rows - 1;   // clamp; dup rows benign

    const float4* __restrict__ srow =
        (const float4*)(scores + (size_t)row * NCOLS);
    float4* __restrict__ orow = (float4*)(out + (size_t)row * NCOLS);

    // per-group smem: double-buffered 4-warp partials (sA, sR)
    __shared__ float2 red[2][NGROUPS][4];

    // ---- load row as float4 (8 LDG.128), group-local min/max ----
    float4 v4[NQUAD];
#pragma unroll
    for (int q = 0; q < NQUAD; q++) v4[q] = srow[gtid + q * GSIZE];

    float mn = v4[0].x, mx = v4[0].x;
#pragma unroll
    for (int q = 0; q < NQUAD; q++) {
        mn = fminf(mn, fminf(fminf(v4[q].x, v4[q].y), fminf(v4[q].z, v4[q].w)));
        mx = fmaxf(mx, fmaxf(fmaxf(v4[q].x, v4[q].y), fmaxf(v4[q].z, v4[q].w)));
    }
#pragma unroll
    for (int off = 16; off; off >>= 1) {
        mn = fminf(mn, __shfl_xor_sync(0xffffffffu, mn, off));
        mx = fmaxf(mx, __shfl_xor_sync(0xffffffffu, mx, off));
    }
    if (lid == 0) red[0][grp][gwid] = make_float2(mn, mx);
    gbar(barid);
#pragma unroll
    for (int w = 0; w < 4; w++) {
        float2 p = red[0][grp][w];
        mn = fminf(mn, p.x);
        mx = fmaxf(mx, p.y);
    }
    gbar(barid);   // fence reads before loop reuses red[0][grp]

    // ---- precompute T_i = 2^{(0.25 - x_i)*SC}, packed pairs ----
    const float SC = 14.426950408889634f;       // (1/eps)*log2(e), eps=0.1
    const float QC = 0.006737946999085467f;     // 2^{-0.5*SC} = e^{-5}
    const float inv = 1.0f / (mx - mn + 1e-12f);

    u64 Tp[NPAIR];
#pragma unroll
    for (int q = 0; q < NQUAD; q++) {
        float t0 = ex2f((0.25f - (v4[q].x - mn) * inv) * SC);
        float t1 = ex2f((0.25f - (v4[q].y - mn) * inv) * SC);
        float t2 = ex2f((0.25f - (v4[q].z - mn) * inv) * SC);
        float t3 = ex2f((0.25f - (v4[q].w - mn) * inv) * SC);
        Tp[2*q]   = pack2(t0, t1);
        Tp[2*q+1] = pack2(t2, t3);
    }

    // ---- Sinkhorn loop: ONE named barrier per iteration ----
    // All threads of the group fold the 4 partials and update E,F,Q with an
    // identical deterministic sequence -> consistent state, no broadcast.
    float E = 1.0f, F = 1.0f, Q = QC;
    float g0 = 0.0f, Qg2 = 0.0f;

    for (int it = 0; it < ITERS; ++it) {
        const u64 Ep = pack2(E, E);
        const u64 Qp = pack2(Q, Q);
        u64 sAp = 0, sRp = 0;
#pragma unroll
        for (int j = 0; j < NPAIR; j++) {
            u64 tp = mulx2(Tp[j], Ep);       // t = T*E
            u64 tq = addx2(tp, Qp);          // t + Q
            u64 dp = fmax2(tp, tp, tq);      // t^2 + t + Q
            float dx, dy; unpack2(dp, dx, dy);
            u64 rp = pack2(rcpf(dx), rcpf(dy));
            sAp = fmax2(tq, rp, sAp);        // += (t+Q)*r
            sRp = addx2(sRp, rp);            // += r
        }
        float ax, ay, rx, ry;
        unpack2(sAp, ax, ay); unpack2(sRp, rx, ry);
        float sA = ax + ay, sR = rx + ry;
#pragma unroll
        for (int off = 16; off; off >>= 1) {
            sA += __shfl_xor_sync(0xffffffffu, sA, off);
            sR += __shfl_xor_sync(0xffffffffu, sR, off);
        }
        const int p = it & 1;
        if (lid == 0) red[p][grp][gwid] = make_float2(sA, sR);
        gbar(barid);

        float2 p0 = red[p][grp][0], p1 = red[p][grp][1];
        float2 p2 = red[p][grp][2], p3 = red[p][grp][3];
        float SA = (p0.x + p1.x) + (p2.x + p3.x);
        float SR = (p0.y + p1.y) + (p2.y + p3.y);

        float S0 = fmaxf((float)NCOLS - SA, 1e-30f);
        float S2 = fmaxf(Q * SR, 1e-30f);
        float S1 = fmaxf(SA - S2, 1e-30f);
        if (it < ITERS - 1) {
            float s = S1 * 0.16666667163372040f;    // S1/6
            E = E * s * rcpf(S0);
            F = F * s * rcpf(S2);
            Q = QC * E * F;
        } else {
            g0  = 512.0f / S0;
            Qg2 = Q * (512.0f / S2);
        }
        // double-buffered red: iter it+2's write to buffer p is separated
        // from iter it's reads by iter it+1's barrier -> 1 barrier/iter.
    }

    // ---- epilogue: out_i = r*(Qg2 - t^2*g0), float4 stores ----
    const u64 Ep = pack2(E, E);
    const u64 Qp = pack2(Q, Q);
#pragma unroll
    for (int q = 0; q < NQUAD; q++) {
        float4 o;
        {
            u64 tp = mulx2(Tp[2*q], Ep);
            u64 tq = addx2(tp, Qp);
            u64 dp = fmax2(tp, tp, tq);
            float dx, dy, tx, ty;
            unpack2(dp, dx, dy); unpack2(tp, tx, ty);
            o.x = rcpf(dx) * fmaf(tx * tx, -g0, Qg2);
            o.y = rcpf(dy) * fmaf(ty * ty, -g0, Qg2);
        }
        {
            u64 tp = mulx2(Tp[2*q+1], Ep);
            u64 tq = addx2(tp, Qp);
            u64 dp = fmax2(tp, tp, tq);
            float dx, dy, tx, ty;
            unpack2(dp, dx, dy); unpack2(tp, tx, ty);
            o.z = rcpf(dx) * fmaf(tx * tx, -g0, Qg2);
            o.w = rcpf(dy) * fmaf(ty * ty, -g0, Qg2);
        }
        orow[gtid + q * GSIZE] = o;
    }
}

extern "C" void kernel_launch(void* const* d_in, const int* in_sizes, int n_in,
                              void* d_out, int out_size)
{
    const float* scores = (const float*)d_in[0];
    float* out = (float*)d_out;
    int rows = in_sizes[0] / NCOLS;                 // 512
    int blocks = (rows + NGROUPS - 1) / NGROUPS;    // 128
    soft_topk_bottomk_kernel<<<blocks, THREADS>>>(scores, out, rows);
}

// round 16
// speedup vs baseline: 31.2241x; 1.1358x over previous
#include <cuda_runtime.h>

// SoftTopKBottomK via Sinkhorn reformulation — warpgroup-per-row, named
// barriers, zero per-element transcendentals in the iteration, float4 I/O,
// DELIBERATE PHASE-SKEW between the 4 independent warpgroups.
//
// Math: t_i = T_i * E with T_i = 2^{(0.25-x_i)*SC} precomputed once.
// Multiplicative potentials: E <- E*s*S2*rc, F <- F*s*S0*rc,
//   rc = 1/(S0*S2), s = S1/6, Q = QC*E*F.
// Per element per iter: t = T*E; d = t^2+t+Q; r = 1/d  (FMUL+FMA+RCP)
//   S0 = N - sum((t+Q)r), S2 = Q*sum(r), S1 = N - S0 - S2
// Output: out_i = r*(Q*g2 - t^2*g0), g_j = 512/S_j (final-pass state).
//
// R15: groups are code-identical -> phase-locked -> all 4 reduction tails
// (~300 cyc serial) align and the MUFU pipe idles every iteration. Groups
// share NO barrier, so a one-time skew of ~grp*380 cyc persists across all
// iterations and staggers the tails under the other groups' compute.
// ITERS=7: transient(10) measured ~7e-7 => transient(7) = 7e-7/lambda^3
// <= ~9e-5 for any lambda >= 0.2.

#define NCOLS   4096
#define THREADS 512
#define NGROUPS 4
#define GSIZE   128         // threads per warpgroup (one row each)
#define NQUAD   8           // float4s per thread: 128*8*4 = 4096
#define NPAIR   16          // packed f32 pairs per thread
#define ITERS   7

typedef unsigned long long u64;

__device__ __forceinline__ float ex2f(float x) {
    float y; asm("ex2.approx.f32 %0, %1;" : "=f"(y) : "f"(x)); return y;
}
__device__ __forceinline__ float rcpf(float x) {
    float y; asm("rcp.approx.f32 %0, %1;" : "=f"(y) : "f"(x)); return y;
}
__device__ __forceinline__ u64 pack2(float lo, float hi) {
    u64 r; asm("mov.b64 %0, {%1, %2};" : "=l"(r) : "f"(lo), "f"(hi)); return r;
}
__device__ __forceinline__ void unpack2(u64 v, float& lo, float& hi) {
    asm("mov.b64 {%0, %1}, %2;" : "=f"(lo), "=f"(hi) : "l"(v));
}
__device__ __forceinline__ u64 addx2(u64 a, u64 b) {
    u64 r; asm("add.rn.f32x2 %0, %1, %2;" : "=l"(r) : "l"(a), "l"(b)); return r;
}
__device__ __forceinline__ u64 mulx2(u64 a, u64 b) {
    u64 r; asm("mul.rn.f32x2 %0, %1, %2;" : "=l"(r) : "l"(a), "l"(b)); return r;
}
__device__ __forceinline__ u64 fmax2(u64 a, u64 b, u64 c) {
    u64 r; asm("fma.rn.f32x2 %0, %1, %2, %3;" : "=l"(r) : "l"(a), "l"(b), "l"(c)); return r;
}
__device__ __forceinline__ void gbar(int id) {
    asm volatile("bar.sync %0, %1;" :: "r"(id), "r"(GSIZE) : "memory");
}

__global__ void __launch_bounds__(THREADS, 1)
soft_topk_bottomk_kernel(const float* __restrict__ scores,
                         float* __restrict__ out, int rows)
{
    const int tid   = threadIdx.x;
    const int grp   = tid >> 7;          // warpgroup 0..3 (warp-aligned)
    const int gtid  = tid & (GSIZE - 1); // thread within group
    const int gwid  = gtid >> 5;         // warp within group 0..3
    const int lid   = tid & 31;
    const int barid = grp + 1;           // named barrier ids 1..4

    int rr = NGROUPS * blockIdx.x + grp;
    const int row = (rr < rows) ? rr : rows - 1;   // clamp; dup rows benign

    const float4* __restrict__ srow =
        (const float4*)(scores + (size_t)row * NCOLS);
    float4* __restrict__ orow = (float4*)(out + (size_t)row * NCOLS);

    // per-group smem: double-buffered 4-warp partials (sA, sR)
    __shared__ float2 red[2][NGROUPS][4];

    // ---- load row as float4 (8 LDG.128), group-local min/max ----
    float4 v4[NQUAD];
#pragma unroll
    for (int q = 0; q < NQUAD; q++) v4[q] = srow[gtid + q * GSIZE];

    float mn = v4[0].x, mx = v4[0].x;
#pragma unroll
    for (int q = 0; q < NQUAD; q++) {
        mn = fminf(mn, fminf(fminf(v4[q].x, v4[q].y), fminf(v4[q].z, v4[q].w)));
        mx = fmaxf(mx, fmaxf(fmaxf(v4[q].x, v4[q].y), fmaxf(v4[q].z, v4[q].w)));
    }
#pragma unroll
    for (int off = 16; off; off >>= 1) {
        mn = fminf(mn, __shfl_xor_sync(0xffffffffu, mn, off));
        mx = fmaxf(mx, __shfl_xor_sync(0xffffffffu, mx, off));
    }
    if (lid == 0) red[0][grp][gwid] = make_float2(mn, mx);
    gbar(barid);
#pragma unroll
    for (int w = 0; w < 4; w++) {
        float2 p = red[0][grp][w];
        mn = fminf(mn, p.x);
        mx = fmaxf(mx, p.y);
    }
    gbar(barid);   // fence reads before loop reuses red[0][grp]

    // ---- precompute T_i = 2^{(0.25 - x_i)*SC}, packed pairs ----
    const float SC = 14.426950408889634f;       // (1/eps)*log2(e), eps=0.1
    const float QC = 0.006737946999085467f;     // 2^{-0.5*SC} = e^{-5}
    const float inv = 1.0f / (mx - mn + 1e-12f);

    u64 Tp[NPAIR];
#pragma unroll
    for (int q = 0; q < NQUAD; q++) {
        float t0 = ex2f((0.25f - (v4[q].x - mn) * inv) * SC);
        float t1 = ex2f((0.25f - (v4[q].y - mn) * inv) * SC);
        float t2 = ex2f((0.25f - (v4[q].z - mn) * inv) * SC);
        float t3 = ex2f((0.25f - (v4[q].w - mn) * inv) * SC);
        Tp[2*q]   = pack2(t0, t1);
        Tp[2*q+1] = pack2(t2, t3);
    }

    // ---- one-time phase skew: grp * ~380 cyc dependent-FADD chain ----
    // Groups share no barrier, so this offset persists for the whole loop
    // and staggers the 4 groups' serial reduction tails under each other's
    // compute phases. Deterministic (fixed trip count per grp).
    {
        float zz = 1.0f;
        const int spin = grp * 64;           // ~6 cyc per dependent iter
        for (int i = 0; i < spin; i++)
            asm volatile("add.f32 %0, %0, %1;" : "+f"(zz) : "f"(inv));
        if (zz == -12345.0f)                 // never true; keeps chain alive
            orow[0] = make_float4(zz, zz, zz, zz);
    }

    // ---- Sinkhorn loop: ONE named barrier per iteration ----
    // All threads of the group fold the 4 partials and update E,F,Q with an
    // identical deterministic sequence -> consistent state, no broadcast.
    float E = 1.0f, F = 1.0f, Q = QC;
    float g0 = 0.0f, Qg2 = 0.0f;

    for (int it = 0; it < ITERS; ++it) {
        const u64 Ep = pack2(E, E);
        const u64 Qp = pack2(Q, Q);
        u64 sAp = 0, sRp = 0;
#pragma unroll
        for (int j = 0; j < NPAIR; j++) {
            u64 tp = mulx2(Tp[j], Ep);       // t = T*E
            u64 tq = addx2(tp, Qp);          // t + Q
            u64 dp = fmax2(tp, tp, tq);      // t^2 + t + Q
            float dx, dy; unpack2(dp, dx, dy);
            u64 rp = pack2(rcpf(dx), rcpf(dy));
            sAp = fmax2(tq, rp, sAp);        // += (t+Q)*r
            sRp = addx2(sRp, rp);            // += r
        }
        float ax, ay, rx, ry;
        unpack2(sAp, ax, ay); unpack2(sRp, rx, ry);
        float sA = ax + ay, sR = rx + ry;
#pragma unroll
        for (int off = 16; off; off >>= 1) {
            sA += __shfl_xor_sync(0xffffffffu, sA, off);
            sR += __shfl_xor_sync(0xffffffffu, sR, off);
        }
        const int p = it & 1;
        if (lid == 0) red[p][grp][gwid] = make_float2(sA, sR);
        gbar(barid);

        float2 p0 = red[p][grp][0], p1 = red[p][grp][1];
        float2 p2 = red[p][grp][2], p3 = red[p][grp][3];
        float SA = (p0.x + p1.x) + (p2.x + p3.x);
        float SR = (p0.y + p1.y) + (p2.y + p3.y);

        float S0 = fmaxf((float)NCOLS - SA, 1e-30f);
        float S2 = fmaxf(Q * SR, 1e-30f);
        float S1 = fmaxf(SA - S2, 1e-30f);
        if (it < ITERS - 1) {
            float s  = S1 * 0.16666667163372040f;   // S1/6
            float rc = rcpf(S0 * S2);               // one MUFU, both updates
            E = E * s * (S2 * rc);
            F = F * s * (S0 * rc);
            Q = QC * E * F;
        } else {
            g0  = 512.0f / S0;
            Qg2 = Q * (512.0f / S2);
        }
        // double-buffered red: iter it+2's write to buffer p is separated
        // from iter it's reads by iter it+1's barrier -> 1 barrier/iter.
    }

    // ---- epilogue: out_i = r*(Qg2 - t^2*g0), float4 stores ----
    const u64 Ep = pack2(E, E);
    const u64 Qp = pack2(Q, Q);
#pragma unroll
    for (int q = 0; q < NQUAD; q++) {
        float4 o;
        {
            u64 tp = mulx2(Tp[2*q], Ep);
            u64 tq = addx2(tp, Qp);
            u64 dp = fmax2(tp, tp, tq);
            float dx, dy, tx, ty;
            unpack2(dp, dx, dy); unpack2(tp, tx, ty);
            o.x = rcpf(dx) * fmaf(tx * tx, -g0, Qg2);
            o.y = rcpf(dy) * fmaf(ty * ty, -g0, Qg2);
        }
        {
            u64 tp = mulx2(Tp[2*q+1], Ep);
            u64 tq = addx2(tp, Qp);
            u64 dp = fmax2(tp, tp, tq);
            float dx, dy, tx, ty;
            unpack2(dp, dx, dy); unpack2(tp, tx, ty);
            o.z = rcpf(dx) * fmaf(tx * tx, -g0, Qg2);
            o.w = rcpf(dy) * fmaf(ty * ty, -g0, Qg2);
        }
        orow[gtid + q * GSIZE] = o;
    }
}

extern "C" void kernel_launch(void* const* d_in, const int* in_sizes, int n_in,
                              void* d_out, int out_size)
{
    const float* scores = (const float*)d_in[0];
    float* out = (float*)d_out;
    int rows = in_sizes[0] / NCOLS;                 // 512
    int blocks = (rows + NGROUPS - 1) / NGROUPS;    // 128
    soft_topk_bottomk_kernel<<<blocks, THREADS>>>(scores, out, rows);
}